// round 11
// baseline (speedup 1.0000x reference)
#include <cuda_runtime.h>
#include <math.h>

#define NN 50000
#define NE 800000
#define F  128
#define NEG_SLOPE 0.2f
#define EPSV 1e-10f

#define NBLK3 49   // ceil(50000/1024)

// ---------------- scratch (device globals; no allocation) ----------------
__device__ __align__(16) float d_Wh[NN * F];     // 25.6 MB
__device__ float d_s1[NN];
__device__ float d_s2[NN];
__device__ __align__(16) int d_rank[NE];         // rank of edge within its row
__device__ int   d_cnt[NN];                      // zero-initialized; re-zeroed by k3
__device__ int   d_off[NN + 1];
__device__ int   d_bagg[NBLK3];
__device__ int   d_bflag[NBLK3];                 // zeroed by k2 each run
__device__ __align__(16) int d_ecol[NE];         // cols in CSR order

// ---------------- packed f32x2 helpers (sm_103a) ----------------
__device__ __forceinline__ void fma2(unsigned long long& d, unsigned long long a,
                                     unsigned long long b) {
    asm("fma.rn.f32x2 %0, %1, %2, %0;" : "+l"(d) : "l"(a), "l"(b));
}
__device__ __forceinline__ unsigned long long pack2(float x) {
    unsigned long long r;
    asm("mov.b64 %0, {%1, %1};" : "=l"(r) : "f"(x));
    return r;
}
__device__ __forceinline__ float2 unpack2(unsigned long long v) {
    float lo, hi;
    asm("mov.b64 {%0, %1}, %2;" : "=f"(lo), "=f"(hi) : "l"(v));
    return make_float2(lo, hi);
}

// ---------------- K1: Wh = h @ W^T (packed f32x2), fused s1/s2 ----------------
// 8 rows per warp; lane owns 4 output features (2 packed pairs).
__global__ void __launch_bounds__(256) k1_gemm(const float* __restrict__ h,
                                               const float* __restrict__ W,
                                               const float* __restrict__ a) {
    extern __shared__ float Ws[];  // 128 * 132 floats; Ws[k*132 + j] = W[j*F + k]
    for (int idx = threadIdx.x; idx < F * F; idx += blockDim.x) {
        int j = idx >> 7;
        int k = idx & 127;
        Ws[k * 132 + j] = W[idx];
    }
    __syncthreads();

    const int lane = threadIdx.x & 31;
    const int wid  = threadIdx.x >> 5;
    int q = blockIdx.x * (blockDim.x >> 5) + wid;   // warp id, 8 rows each
    const int nq = NN / 8;  // 6250
    if (q >= nq) return;

    const ulonglong2* WsU = (const ulonglong2*)Ws;   // row stride 33 ulonglong2
    const float4* h40 = ((const float4*)h) + (size_t)q * 8 * 32;

    unsigned long long aLo[8] = {0,0,0,0,0,0,0,0};
    unsigned long long aHi[8] = {0,0,0,0,0,0,0,0};

#pragma unroll 2
    for (int k4 = 0; k4 < 32; k4++) {
        float4 hv[8];
#pragma unroll
        for (int t = 0; t < 8; t++) hv[t] = __ldg(h40 + t * 32 + k4);
#pragma unroll
        for (int kk = 0; kk < 4; kk++) {
            ulonglong2 wv = WsU[(k4 * 4 + kk) * 33 + lane];
#pragma unroll
            for (int t = 0; t < 8; t++) {
                unsigned long long b = pack2(((const float*)&hv[t])[kk]);
                fma2(aLo[t], b, wv.x);
                fma2(aHi[t], b, wv.y);
            }
        }
    }

    int r0 = q * 8;
    float4* Wh4 = (float4*)d_Wh;
    float4 av1 = __ldg(&((const float4*)a)[lane]);        // a1
    float4 av2 = __ldg(&((const float4*)a)[32 + lane]);   // a2
    float p1[8], p2[8];
#pragma unroll
    for (int t = 0; t < 8; t++) {
        float2 lo = unpack2(aLo[t]);
        float2 hi = unpack2(aHi[t]);
        float4 v = make_float4(lo.x, lo.y, hi.x, hi.y);
        Wh4[(size_t)(r0 + t) * 32 + lane] = v;
        p1[t] = v.x*av1.x + v.y*av1.y + v.z*av1.z + v.w*av1.w;
        p2[t] = v.x*av2.x + v.y*av2.y + v.z*av2.z + v.w*av2.w;
    }
#pragma unroll
    for (int d = 16; d; d >>= 1) {
#pragma unroll
        for (int t = 0; t < 8; t++) {
            p1[t] += __shfl_xor_sync(0xffffffffu, p1[t], d);
            p2[t] += __shfl_xor_sync(0xffffffffu, p2[t], d);
        }
    }
    if (lane == 0) {
#pragma unroll
        for (int t = 0; t < 8; t++) {
            d_s1[r0 + t] = p1[t];
            d_s2[r0 + t] = p2[t];
        }
    }
}

// ---------------- K2: counts (4 edges/thread, MLP=4); zero scan flags ----------------
__global__ void k2_count(const int* __restrict__ rows) {
    int i = blockIdx.x * blockDim.x + threadIdx.x;     // edge-quad index
    if (i < NBLK3) d_bflag[i] = 0;                     // reset lookback flags
    if (i >= NE / 4) return;
    int4 r4 = __ldg(&((const int4*)rows)[i]);
    int rk0 = atomicAdd(&d_cnt[r4.x], 1);
    int rk1 = atomicAdd(&d_cnt[r4.y], 1);
    int rk2 = atomicAdd(&d_cnt[r4.z], 1);
    int rk3 = atomicAdd(&d_cnt[r4.w], 1);
    ((int4*)d_rank)[i] = make_int4(rk0, rk1, rk2, rk3);
}

// ---------------- K3: single-kernel exclusive scan (parallel lookback) ----------------
__global__ void __launch_bounds__(1024) k3_scan() {
    int tid = threadIdx.x, lane = tid & 31, wid = tid >> 5;
    int b = blockIdx.x;
    int i = b * 1024 + tid;
    int v = (i < NN) ? d_cnt[i] : 0;
    if (i < NN) d_cnt[i] = 0;   // restore invariant for next replay

    int incl = v;
#pragma unroll
    for (int d = 1; d < 32; d <<= 1) {
        int t = __shfl_up_sync(0xffffffffu, incl, d);
        if (lane >= d) incl += t;
    }
    __shared__ int ws[32];
    __shared__ int s_pref;
    if (lane == 31) ws[wid] = incl;
    __syncthreads();
    if (wid == 0) {
        int wv = ws[lane];
        int wincl = wv;
#pragma unroll
        for (int d = 1; d < 32; d <<= 1) {
            int t = __shfl_up_sync(0xffffffffu, wincl, d);
            if (lane >= d) wincl += t;
        }
        ws[lane] = wincl - wv;
    }
    __syncthreads();
    int excl = ws[wid] + incl - v;

    if (tid == 1023) {
        d_bagg[b] = excl + v;
        __threadfence();
        atomicExch(&d_bflag[b], 1);
    }

    if (wid == 0) {
        int p = 0;
        for (int j = lane; j < b; j += 32) {
            while (atomicAdd(&d_bflag[j], 0) == 0) { }
            p += d_bagg[j];
        }
#pragma unroll
        for (int d = 16; d; d >>= 1) p += __shfl_xor_sync(0xffffffffu, p, d);
        if (lane == 0) s_pref = p;
    }
    __syncthreads();
    if (i <= NN) d_off[i] = s_pref + excl;
}

// ---------------- K4: scatter cols into CSR order (4 edges/thread, MLP=4) ----------------
__global__ void k4_scatter(const int* __restrict__ rows, const int* __restrict__ cols) {
    int i = blockIdx.x * blockDim.x + threadIdx.x;
    if (i >= NE / 4) return;
    int4 r4 = __ldg(&((const int4*)rows)[i]);
    int4 k4 = ((const int4*)d_rank)[i];
    int4 c4 = __ldg(&((const int4*)cols)[i]);
    int p0 = d_off[r4.x] + k4.x;
    int p1 = d_off[r4.y] + k4.y;
    int p2 = d_off[r4.z] + k4.z;
    int p3 = d_off[r4.w] + k4.w;
    d_ecol[p0] = c4.x;
    d_ecol[p1] = c4.y;
    d_ecol[p2] = c4.z;
    d_ecol[p3] = c4.w;
}

// ---------------- K5: per-row softmax + aggregation + elu (one warp per row) ----------------
// Chunk of (col, exp) staged via shared (LDS broadcast), packed f32x2 accumulate.
__global__ void __launch_bounds__(256) k5_agg(float* __restrict__ out) {
    __shared__ int2 sbuf[8][32];
    const int wid  = threadIdx.x >> 5;
    const int lane = threadIdx.x & 31;
    int r = blockIdx.x * (blockDim.x >> 5) + wid;
    if (r >= NN) return;
    int s = d_off[r], e = d_off[r + 1];
    float s1r = d_s1[r];
    unsigned long long accLo = 0, accHi = 0;
    float sum = 0.f;
    const ulonglong2* WhU = (const ulonglong2*)d_Wh;   // 32 x 16B per row

    for (int base = s; base < e; base += 32) {
        int n = e - base; if (n > 32) n = 32;
        if (lane < n) {
            int cl = d_ecol[base + lane];
            float sv = s1r + __ldg(&d_s2[cl]);
            float ev = sv > 0.f ? sv : NEG_SLOPE * sv;
            sbuf[wid][lane] = make_int2(cl, __float_as_int(__expf(ev)));
        }
        __syncwarp();
#pragma unroll 4
        for (int t = 0; t < n; t++) {
            int2 p = sbuf[wid][t];                    // LDS.64 broadcast
            float av = __int_as_float(p.y);
            sum += av;
            unsigned long long avp = pack2(av);
            ulonglong2 w = WhU[(size_t)p.x * 32 + lane];
            fma2(accLo, avp, w.x);
            fma2(accHi, avp, w.y);
        }
        __syncwarp();
    }

    float inv = 1.f / (sum + EPSV);
    float2 lo = unpack2(accLo);
    float2 hi = unpack2(accHi);
    float4 acc = make_float4(lo.x * inv, lo.y * inv, hi.x * inv, hi.y * inv);
    acc.x = acc.x > 0.f ? acc.x : expm1f(acc.x);
    acc.y = acc.y > 0.f ? acc.y : expm1f(acc.y);
    acc.z = acc.z > 0.f ? acc.z : expm1f(acc.z);
    acc.w = acc.w > 0.f ? acc.w : expm1f(acc.w);
    ((float4*)out)[(size_t)r * 32 + lane] = acc;
}

// ---------------- launch ----------------
extern "C" void kernel_launch(void* const* d_in, const int* in_sizes, int n_in,
                              void* d_out, int out_size) {
    const float* h  = (const float*)d_in[0];
    const int*   ei = (const int*)d_in[1];
    const float* W  = (const float*)d_in[2];
    const float* a  = (const float*)d_in[3];
    const int* rows = ei;
    const int* cols = ei + NE;
    float* out = (float*)d_out;

    static cudaStream_t s2 = nullptr;
    static cudaEvent_t evFork = nullptr, evJoin = nullptr;
    if (s2 == nullptr) {
        cudaStreamCreateWithFlags(&s2, cudaStreamNonBlocking);
        cudaEventCreateWithFlags(&evFork, cudaEventDisableTiming);
        cudaEventCreateWithFlags(&evJoin, cudaEventDisableTiming);
    }

    cudaFuncSetAttribute(k1_gemm, cudaFuncAttributeMaxDynamicSharedMemorySize, 128 * 132 * 4);

    // Fork: CSR build (structure only) runs concurrently with the GEMM.
    cudaEventRecord(evFork, 0);
    cudaStreamWaitEvent(s2, evFork, 0);

    k1_gemm<<<(NN / 8 + 7) / 8, 256, 128 * 132 * 4>>>(h, W, a);   // main stream

    k2_count<<<(NE / 4 + 255) / 256, 256, 0, s2>>>(rows);
    k3_scan<<<NBLK3, 1024, 0, s2>>>();
    k4_scatter<<<(NE / 4 + 255) / 256, 256, 0, s2>>>(rows, cols);
    cudaEventRecord(evJoin, s2);

    // Join: k5 needs Wh/s1/s2 (main) + CSR (s2).
    cudaStreamWaitEvent(0, evJoin, 0);
    k5_agg<<<(NN + 7) / 8, 256>>>(out);
}

// round 14
// speedup vs baseline: 1.0787x; 1.0787x over previous
#include <cuda_runtime.h>
#include <math.h>

#define NN 50000
#define NE 800000
#define F  128
#define NEG_SLOPE 0.2f
#define EPSV 1e-10f

#define NBLK3 49   // ceil(50000/1024)

// ---------------- scratch (device globals; no allocation) ----------------
__device__ __align__(16) float d_Wh[NN * F];     // 25.6 MB
__device__ float d_s1[NN];
__device__ float d_s2[NN];
__device__ int   d_cnt[NN];                      // zero-initialized; re-zeroed by k3
__device__ int   d_off[NN + 1];
__device__ int   d_cur[NN];                      // working copy; consumed by k4 each run
__device__ int   d_bagg[NBLK3];
__device__ int   d_bflag[NBLK3];                 // zeroed by k2 each run
__device__ __align__(16) int d_ecol[NE];         // cols in CSR order

// ---------------- packed f32x2 helpers (sm_103a) ----------------
__device__ __forceinline__ void fma2(unsigned long long& d, unsigned long long a,
                                     unsigned long long b) {
    asm("fma.rn.f32x2 %0, %1, %2, %0;" : "+l"(d) : "l"(a), "l"(b));
}
__device__ __forceinline__ unsigned long long pack2(float x) {
    unsigned long long r;
    asm("mov.b64 %0, {%1, %1};" : "=l"(r) : "f"(x));
    return r;
}
__device__ __forceinline__ float2 unpack2(unsigned long long v) {
    float lo, hi;
    asm("mov.b64 {%0, %1}, %2;" : "=f"(lo), "=f"(hi) : "l"(v));
    return make_float2(lo, hi);
}

// ---------------- K1: Wh = h @ W^T (packed f32x2), fused s1/s2 ----------------
// 8 rows per warp; lane owns 4 output features (2 packed pairs).
__global__ void __launch_bounds__(256) k1_gemm(const float* __restrict__ h,
                                               const float* __restrict__ W,
                                               const float* __restrict__ a) {
    extern __shared__ float Ws[];  // 128 * 132 floats; Ws[k*132 + j] = W[j*F + k]
    for (int idx = threadIdx.x; idx < F * F; idx += blockDim.x) {
        int j = idx >> 7;
        int k = idx & 127;
        Ws[k * 132 + j] = W[idx];
    }
    __syncthreads();

    const int lane = threadIdx.x & 31;
    const int wid  = threadIdx.x >> 5;
    int q = blockIdx.x * (blockDim.x >> 5) + wid;   // warp id, 8 rows each
    const int nq = NN / 8;  // 6250
    if (q >= nq) return;

    const ulonglong2* WsU = (const ulonglong2*)Ws;   // row stride 33 ulonglong2
    const float4* h40 = ((const float4*)h) + (size_t)q * 8 * 32;

    unsigned long long aLo[8] = {0,0,0,0,0,0,0,0};
    unsigned long long aHi[8] = {0,0,0,0,0,0,0,0};

#pragma unroll 2
    for (int k4 = 0; k4 < 32; k4++) {
        float4 hv[8];
#pragma unroll
        for (int t = 0; t < 8; t++) hv[t] = __ldg(h40 + t * 32 + k4);
#pragma unroll
        for (int kk = 0; kk < 4; kk++) {
            ulonglong2 wv = WsU[(k4 * 4 + kk) * 33 + lane];
#pragma unroll
            for (int t = 0; t < 8; t++) {
                unsigned long long b = pack2(((const float*)&hv[t])[kk]);
                fma2(aLo[t], b, wv.x);
                fma2(aHi[t], b, wv.y);
            }
        }
    }

    int r0 = q * 8;
    float4* Wh4 = (float4*)d_Wh;
    float4 av1 = __ldg(&((const float4*)a)[lane]);        // a1
    float4 av2 = __ldg(&((const float4*)a)[32 + lane]);   // a2
    float p1[8], p2[8];
#pragma unroll
    for (int t = 0; t < 8; t++) {
        float2 lo = unpack2(aLo[t]);
        float2 hi = unpack2(aHi[t]);
        float4 v = make_float4(lo.x, lo.y, hi.x, hi.y);
        Wh4[(size_t)(r0 + t) * 32 + lane] = v;
        p1[t] = v.x*av1.x + v.y*av1.y + v.z*av1.z + v.w*av1.w;
        p2[t] = v.x*av2.x + v.y*av2.y + v.z*av2.z + v.w*av2.w;
    }
#pragma unroll
    for (int d = 16; d; d >>= 1) {
#pragma unroll
        for (int t = 0; t < 8; t++) {
            p1[t] += __shfl_xor_sync(0xffffffffu, p1[t], d);
            p2[t] += __shfl_xor_sync(0xffffffffu, p2[t], d);
        }
    }
    if (lane == 0) {
#pragma unroll
        for (int t = 0; t < 8; t++) {
            d_s1[r0 + t] = p1[t];
            d_s2[r0 + t] = p2[t];
        }
    }
}

// ---------------- K2: per-row counts only; zero scan flags ----------------
__global__ void k2_count(const int* __restrict__ rows) {
    int i = blockIdx.x * blockDim.x + threadIdx.x;
    if (i < NBLK3) d_bflag[i] = 0;   // reset lookback flags for this replay
    if (i >= NE) return;
    atomicAdd(&d_cnt[__ldg(&rows[i])], 1);
}

// ---------------- K3: single-kernel exclusive scan (parallel lookback) ----------------
// 49 blocks x 1024, all co-resident (< 148 SMs) -> spin-wait is deadlock-free.
// Writes d_off AND the working copy d_cur (consumed by k4 each run).
__global__ void __launch_bounds__(1024) k3_scan() {
    int tid = threadIdx.x, lane = tid & 31, wid = tid >> 5;
    int b = blockIdx.x;
    int i = b * 1024 + tid;
    int v = (i < NN) ? d_cnt[i] : 0;
    if (i < NN) d_cnt[i] = 0;   // restore invariant for next replay

    int incl = v;
#pragma unroll
    for (int d = 1; d < 32; d <<= 1) {
        int t = __shfl_up_sync(0xffffffffu, incl, d);
        if (lane >= d) incl += t;
    }
    __shared__ int ws[32];
    __shared__ int s_pref;
    if (lane == 31) ws[wid] = incl;
    __syncthreads();
    if (wid == 0) {
        int wv = ws[lane];
        int wincl = wv;
#pragma unroll
        for (int d = 1; d < 32; d <<= 1) {
            int t = __shfl_up_sync(0xffffffffu, wincl, d);
            if (lane >= d) wincl += t;
        }
        ws[lane] = wincl - wv;
    }
    __syncthreads();
    int excl = ws[wid] + incl - v;

    if (tid == 1023) {
        d_bagg[b] = excl + v;
        __threadfence();
        atomicExch(&d_bflag[b], 1);
    }

    if (wid == 0) {
        int p = 0;
        for (int j = lane; j < b; j += 32) {
            while (atomicAdd(&d_bflag[j], 0) == 0) { }
            p += d_bagg[j];
        }
#pragma unroll
        for (int d = 16; d; d >>= 1) p += __shfl_xor_sync(0xffffffffu, p, d);
        if (lane == 0) s_pref = p;
    }
    __syncthreads();
    int o = s_pref + excl;
    if (i <= NN) d_off[i] = o;
    if (i < NN)  d_cur[i] = o;
}

// ---------------- K4: scatter cols into CSR order (atomic position claim) ----------------
__global__ void k4_scatter(const int* __restrict__ rows, const int* __restrict__ cols) {
    int i = blockIdx.x * blockDim.x + threadIdx.x;
    if (i >= NE) return;
    int r = __ldg(&rows[i]);
    int pos = atomicAdd(&d_cur[r], 1);
    d_ecol[pos] = __ldg(&cols[i]);
}

// ---------------- K5: per-row softmax + aggregation + elu (one warp per row) ----------------
// Coalesced chunk load of cols; per-lane s2 gather + exp; shuffle-distributed
// addresses -> all Wh gathers in a chunk are independent (MLP ~= degree).
__global__ void k5_agg(float* __restrict__ out) {
    int r    = blockIdx.x * (blockDim.x >> 5) + (threadIdx.x >> 5);
    int lane = threadIdx.x & 31;
    if (r >= NN) return;
    int s = d_off[r], e = d_off[r + 1];
    float s1r = d_s1[r];
    float4 acc = make_float4(0.f, 0.f, 0.f, 0.f);
    float sum = 0.f;
    const float4* Wh4 = (const float4*)d_Wh;

    for (int base = s; base < e; base += 32) {
        int n = e - base; if (n > 32) n = 32;
        int   cl = 0;
        float ex = 0.f;
        if (lane < n) {
            cl = d_ecol[base + lane];
            float sv = s1r + __ldg(&d_s2[cl]);
            float ev = sv > 0.f ? sv : NEG_SLOPE * sv;
            ex = __expf(ev);
        }
#pragma unroll 4
        for (int t = 0; t < n; t++) {
            int   c  = __shfl_sync(0xffffffffu, cl, t);
            float av = __shfl_sync(0xffffffffu, ex, t);
            sum += av;
            float4 w = Wh4[(size_t)c * 32 + lane];
            acc.x = fmaf(av, w.x, acc.x); acc.y = fmaf(av, w.y, acc.y);
            acc.z = fmaf(av, w.z, acc.z); acc.w = fmaf(av, w.w, acc.w);
        }
    }

    float inv = 1.f / (sum + EPSV);
    acc.x *= inv; acc.y *= inv; acc.z *= inv; acc.w *= inv;
    acc.x = acc.x > 0.f ? acc.x : expm1f(acc.x);
    acc.y = acc.y > 0.f ? acc.y : expm1f(acc.y);
    acc.z = acc.z > 0.f ? acc.z : expm1f(acc.z);
    acc.w = acc.w > 0.f ? acc.w : expm1f(acc.w);
    ((float4*)out)[(size_t)r * 32 + lane] = acc;
}

// ---------------- launch ----------------
extern "C" void kernel_launch(void* const* d_in, const int* in_sizes, int n_in,
                              void* d_out, int out_size) {
    const float* h  = (const float*)d_in[0];
    const int*   ei = (const int*)d_in[1];
    const float* W  = (const float*)d_in[2];
    const float* a  = (const float*)d_in[3];
    const int* rows = ei;
    const int* cols = ei + NE;
    float* out = (float*)d_out;

    static cudaStream_t s2 = nullptr;
    static cudaEvent_t evFork = nullptr, evJoin = nullptr;
    if (s2 == nullptr) {
        cudaStreamCreateWithFlags(&s2, cudaStreamNonBlocking);
        cudaEventCreateWithFlags(&evFork, cudaEventDisableTiming);
        cudaEventCreateWithFlags(&evJoin, cudaEventDisableTiming);
    }

    cudaFuncSetAttribute(k1_gemm, cudaFuncAttributeMaxDynamicSharedMemorySize, 128 * 132 * 4);

    // Fork: CSR build (structure only) runs concurrently with the GEMM.
    cudaEventRecord(evFork, 0);
    cudaStreamWaitEvent(s2, evFork, 0);

    k1_gemm<<<(NN / 8 + 7) / 8, 256, 128 * 132 * 4>>>(h, W, a);   // main stream

    k2_count<<<(NE + 255) / 256, 256, 0, s2>>>(rows);
    k3_scan<<<NBLK3, 1024, 0, s2>>>();
    k4_scatter<<<(NE + 255) / 256, 256, 0, s2>>>(rows, cols);
    cudaEventRecord(evJoin, s2);

    // Join: k5 needs Wh/s1/s2 (main) + CSR (s2).
    cudaStreamWaitEvent(0, evJoin, 0);
    k5_agg<<<(NN + 7) / 8, 256>>>(out);
}